// round 7
// baseline (speedup 1.0000x reference)
#include <cuda_runtime.h>
#include <cstdint>

// NCA: x[8,20,256,256], W1[128,60], b1[128], W2[20,128], steps=64

#define BB 8
#define CC 20
#define HH 256
#define WW 256
#define KH 128
#define TILE_W 32
#define TILE_H 8
#define NTHREADS 256

#define XS_ELEMS   (CC*10*34)     // 6800
#define W1_ELEMS   (KH*60)        // 7680
#define W2_ELEMS   (KH*20)        // 2560
#define SMEM_BYTES  (XS_ELEMS*4 + (NTHREADS+1)*4)   // ~28.2 KB

__device__ float g_bufA[BB*CC*HH*WW];
__device__ float g_bufB[BB*CC*HH*WW];
__device__ float g_W2T[W2_ELEMS];

// Weights in constant bank: warp-uniform indices -> LDCU path (uniform port),
// freeing the L1/smem crossbar entirely for perceive traffic.
__constant__ float cW1[W1_ELEMS];   // [128][60] row-major, 240B rows
__constant__ float cW2T[W2_ELEMS];  // [128][20] k-major
__constant__ float cb1[KH];

typedef unsigned long long u64;
struct ull2 { u64 x, y; };

__device__ __forceinline__ u64 fma2(u64 a, u64 b, u64 c) {
    u64 d;
    asm("fma.rn.f32x2 %0, %1, %2, %3;" : "=l"(d) : "l"(a), "l"(b), "l"(c));
    return d;
}
__device__ __forceinline__ u64 pack2(float lo, float hi) {
    u64 r;
    asm("mov.b64 %0, {%1, %2};" : "=l"(r) : "f"(lo), "f"(hi));
    return r;
}
__device__ __forceinline__ void unpack2(float& lo, float& hi, u64 v) {
    asm("mov.b64 {%0, %1}, %2;" : "=f"(lo), "=f"(hi) : "l"(v));
}

__device__ __forceinline__ uint32_t rotl32(uint32_t v, int r) {
    return (v << r) | (v >> (32 - r));
}

// JAX threefry2x32 (20 rounds), bit-exact.
__device__ __forceinline__ void tf2x32(uint32_t k0, uint32_t k1,
                                       uint32_t& x0, uint32_t& x1) {
    uint32_t ks2 = k0 ^ k1 ^ 0x1BD11BDAu;
    x0 += k0; x1 += k1;
#define TFR(r) { x0 += x1; x1 = rotl32(x1, r); x1 ^= x0; }
    TFR(13) TFR(15) TFR(26) TFR(6)
    x0 += k1; x1 += ks2 + 1u;
    TFR(17) TFR(29) TFR(16) TFR(24)
    x0 += ks2; x1 += k0 + 2u;
    TFR(13) TFR(15) TFR(26) TFR(6)
    x0 += k0; x1 += k1 + 3u;
    TFR(17) TFR(29) TFR(16) TFR(24)
    x0 += k1; x1 += ks2 + 4u;
    TFR(13) TFR(15) TFR(26) TFR(6)
    x0 += ks2; x1 += k0 + 5u;
#undef TFR
}

__device__ __forceinline__ int refl(int v, int n) {
    v = (v < 0) ? -v : v;
    return (v >= n) ? (2 * n - 2 - v) : v;
}

__global__ void transposeW2(const float* __restrict__ W2) {
    int i = blockIdx.x * blockDim.x + threadIdx.x;   // i = k*20 + c
    if (i < W2_ELEMS) {
        int k = i / 20, c = i - k * 20;
        g_W2T[i] = W2[c * KH + k];
    }
}

__global__ void __launch_bounds__(NTHREADS, 2)
nca_step(const float* __restrict__ in, float* __restrict__ out, int step)
{
    extern __shared__ float sm[];
    float* xs  = sm;                      // [20][10][34]
    int*   lst = (int*)(xs + XS_ELEMS);   // [256] firing pixel ids
    int*   cntp = lst + NTHREADS;

    const int tid = threadIdx.x;
    const int bz  = blockIdx.z;
    const int by0 = blockIdx.y * TILE_H;
    const int bx0 = blockIdx.x * TILE_W;

    if (tid == 0) *cntp = 0;

    // ---- stage x tile (reflect halo) ----
    const float* inb = in + bz * (CC * HH * WW);
    for (int i = tid; i < XS_ELEMS; i += NTHREADS) {
        int c   = i / 340;
        int rem = i - c * 340;
        int yy  = rem / 34;
        int xx  = rem - yy * 34;
        int gy  = refl(by0 + yy - 1, HH);
        int gx  = refl(bx0 + xx - 1, WW);
        xs[i] = inb[(c << 16) + (gy << 8) + gx];
    }
    __syncthreads();

    const int tx = tid & 31, ty = tid >> 5;
    const int gy = by0 + ty, gx = bx0 + tx;
    const int pidx = (bz << 16) + (gy << 8) + gx;

    // ---- fire mask (partitionable threefry, XOR-fold) ----
    uint32_t s0 = 0u, s1 = (uint32_t)step;
    tf2x32(0u, 42u, s0, s1);                   // fold_in(key(42), step)
    uint32_t r0 = 0u, r1 = (uint32_t)pidx;     // block = (0, flat_idx)
    tf2x32(s0, s1, r0, r1);
    bool fire = ((r0 ^ r1) & 0x80000000u) == 0u;

    float* outb = out + bz * (CC * HH * WW);

    if (!fire) {
        #pragma unroll
        for (int c = 0; c < CC; c++)
            outb[(c << 16) + (gy << 8) + gx] = xs[(c * 10 + ty + 1) * 34 + tx + 1];
    } else {
        int pos = atomicAdd(cntp, 1);
        lst[pos] = tid;
    }
    __syncthreads();

    const int F = *cntp;
    if (tid < F) {
        const int pid = lst[tid];
        const int px = pid & 31, py = pid >> 5;

        // perceive -> packed pairs pp[30]
        // pp[0..9]  = (cen[2j], cen[2j+1]);  pp[10+c] = (gx_c, gy_c)
        u64 pp[30];
        float cen[20];
        #pragma unroll
        for (int c = 0; c < CC; c++) {
            const float* b = xs + (c * 10 + py) * 34 + px;
            float a00 = b[0],  a01 = b[1],  a02 = b[2];
            float a10 = b[34], a11 = b[35], a12 = b[36];
            float a20 = b[68], a21 = b[69], a22 = b[70];
            cen[c] = a11;
            float gxv = (a02 - a00 + 2.f * (a12 - a10) + a22 - a20) * 0.125f;
            float gyv = (a20 - a00 + 2.f * (a21 - a01) + a22 - a02) * 0.125f;
            pp[10 + c] = pack2(gxv, gyv);
        }
        #pragma unroll
        for (int j = 0; j < 10; j++) pp[j] = pack2(cen[2*j], cen[2*j+1]);

        u64 dxp[10];
        #pragma unroll
        for (int j = 0; j < 10; j++) dxp[j] = 0ull;

        #pragma unroll 4
        for (int k = 0; k < KH; k++) {
            const ull2* wr = (const ull2*)(cW1 + k * 60);   // 15 x 16B, uniform addr
            u64 a0 = 0ull, a1 = 0ull, a2 = 0ull, a3 = 0ull;
            #pragma unroll
            for (int q = 0; q < 15; q += 2) {
                ull2 w = wr[q];
                a0 = fma2(w.x, pp[2*q+0], a0);
                a1 = fma2(w.y, pp[2*q+1], a1);
                if (q + 1 < 15) {
                    ull2 w2 = wr[q+1];
                    a2 = fma2(w2.x, pp[2*q+2], a2);
                    a3 = fma2(w2.y, pp[2*q+3], a3);
                }
            }
            float l0, h0, l1, h1, l2, h2, l3, h3;
            unpack2(l0, h0, a0); unpack2(l1, h1, a1);
            unpack2(l2, h2, a2); unpack2(l3, h3, a3);
            float hk = ((l0 + h0) + (l1 + h1)) + ((l2 + h2) + (l3 + h3)) + cb1[k];
            hk = fmaxf(hk, 0.f);
            u64 hk2 = pack2(hk, hk);
            const ull2* w2r = (const ull2*)(cW2T + k * 20); // 5 x 16B, uniform addr
            #pragma unroll
            for (int q = 0; q < 5; q++) {
                ull2 w = w2r[q];
                dxp[2*q+0] = fma2(w.x, hk2, dxp[2*q+0]);
                dxp[2*q+1] = fma2(w.y, hk2, dxp[2*q+1]);
            }
        }

        float dx[20];
        #pragma unroll
        for (int j = 0; j < 10; j++) unpack2(dx[2*j], dx[2*j+1], dxp[j]);

        const int ggy = by0 + py, ggx = bx0 + px;
        #pragma unroll
        for (int c = 0; c < CC; c++) {
            float v = cen[c];
            if (c >= 3) v += dx[c];           // image channels immutable
            outb[(c << 16) + (ggy << 8) + ggx] = v;
        }
    }
}

extern "C" void kernel_launch(void* const* d_in, const int* in_sizes, int n_in,
                              void* d_out, int out_size) {
    // Identify inputs by unique element counts:
    // x=10485760, W1=7680, b1=128, W2=2560, steps=1
    const float* x = nullptr; const float* W1 = nullptr;
    const float* b1 = nullptr; const float* W2 = nullptr;
    for (int i = 0; i < n_in; i++) {
        switch (in_sizes[i]) {
            case BB*CC*HH*WW: x  = (const float*)d_in[i]; break;
            case W1_ELEMS:    W1 = (const float*)d_in[i]; break;
            case KH:          b1 = (const float*)d_in[i]; break;
            case W2_ELEMS:    W2 = (const float*)d_in[i]; break;
            default: break; // steps scalar; fixed at 64
        }
    }
    float* out = (float*)d_out;

    float *bufA = nullptr, *bufB = nullptr, *w2t = nullptr;
    cudaGetSymbolAddress((void**)&bufA, g_bufA);
    cudaGetSymbolAddress((void**)&bufB, g_bufB);
    cudaGetSymbolAddress((void**)&w2t,  g_W2T);

    // Stage weights into constant bank (graph-capturable D2D copies).
    transposeW2<<<(W2_ELEMS + 255) / 256, 256>>>(W2);
    cudaMemcpyToSymbolAsync(cW1,  W1,  W1_ELEMS * 4, 0, cudaMemcpyDeviceToDevice, 0);
    cudaMemcpyToSymbolAsync(cW2T, w2t, W2_ELEMS * 4, 0, cudaMemcpyDeviceToDevice, 0);
    cudaMemcpyToSymbolAsync(cb1,  b1,  KH * 4,       0, cudaMemcpyDeviceToDevice, 0);

    cudaFuncSetAttribute(nca_step, cudaFuncAttributeMaxDynamicSharedMemorySize,
                         SMEM_BYTES);

    dim3 grid(WW / TILE_W, HH / TILE_H, BB);   // (8, 32, 8) = 2048 blocks
    const int STEPS = 64;
    for (int s = 0; s < STEPS; s++) {
        const float* src = (s == 0) ? x : ((s & 1) ? bufA : bufB);
        float* dst = (s == STEPS - 1) ? out : ((s & 1) ? bufB : bufA);
        nca_step<<<grid, NTHREADS, SMEM_BYTES>>>(src, dst, s);
    }
}

// round 9
// speedup vs baseline: 1.2123x; 1.2123x over previous
#include <cuda_runtime.h>
#include <cstdint>

// NCA: x[8,20,256,256], W1[128,60], b1[128], W2[20,128], steps=64
// Tensor path via classic mma.sync (tf32, m16n8k8) — legal on base sm_103 target.

#define BB 8
#define CC 20
#define HH 256
#define WW 256
#define KH 128

#define TILE_W 32
#define TILE_H 4
#define NTHREADS 128
#define NPIX 128

#define XS_ROWS 6
#define XS_ELEMS (CC*XS_ROWS*34)   // 4080
#define P_STRIDE 68
#define W1_STRIDE 68
#define W2_STRIDE 132

#define P_OFF  4080                         // 16B aligned (4080*4)
#define W1_OFF (P_OFF + NPIX*P_STRIDE)      // 12784
#define W2_OFF (W1_OFF + KH*W1_STRIDE)      // 21488
#define B1_OFF (W2_OFF + 24*W2_STRIDE)      // 24656
#define SMEM_FLOATS (B1_OFF + KH)           // 24784
#define SMEM_BYTES (SMEM_FLOATS*4)          // ~96.8 KB -> 2 blocks/SM

__device__ float g_bufA[BB*CC*HH*WW];
__device__ float g_bufB[BB*CC*HH*WW];

__device__ __forceinline__ uint32_t tf32r(float f) {
    uint32_t r;
    asm("cvt.rna.tf32.f32 %0, %1;" : "=r"(r) : "f"(f));
    return r;
}

__device__ __forceinline__ void mma8(float* c, const uint32_t* a,
                                     uint32_t b0, uint32_t b1) {
    asm volatile(
        "mma.sync.aligned.m16n8k8.row.col.f32.tf32.tf32.f32 "
        "{%0,%1,%2,%3}, {%4,%5,%6,%7}, {%8,%9}, {%0,%1,%2,%3};"
        : "+f"(c[0]), "+f"(c[1]), "+f"(c[2]), "+f"(c[3])
        : "r"(a[0]), "r"(a[1]), "r"(a[2]), "r"(a[3]), "r"(b0), "r"(b1));
}

__device__ __forceinline__ uint32_t rotl32(uint32_t v, int r) {
    return (v << r) | (v >> (32 - r));
}
// JAX threefry2x32 (20 rounds), bit-exact.
__device__ __forceinline__ void tf2x32(uint32_t k0, uint32_t k1,
                                       uint32_t& x0, uint32_t& x1) {
    uint32_t ks2 = k0 ^ k1 ^ 0x1BD11BDAu;
    x0 += k0; x1 += k1;
#define TFR(r) { x0 += x1; x1 = rotl32(x1, r); x1 ^= x0; }
    TFR(13) TFR(15) TFR(26) TFR(6)
    x0 += k1; x1 += ks2 + 1u;
    TFR(17) TFR(29) TFR(16) TFR(24)
    x0 += ks2; x1 += k0 + 2u;
    TFR(13) TFR(15) TFR(26) TFR(6)
    x0 += k0; x1 += k1 + 3u;
    TFR(17) TFR(29) TFR(16) TFR(24)
    x0 += k1; x1 += ks2 + 4u;
    TFR(13) TFR(15) TFR(26) TFR(6)
    x0 += ks2; x1 += k0 + 5u;
#undef TFR
}
__device__ __forceinline__ int refl(int v, int n) {
    v = (v < 0) ? -v : v;
    return (v >= n) ? (2 * n - 2 - v) : v;
}

__global__ void __launch_bounds__(NTHREADS, 2)
nca_step(const float* __restrict__ in, float* __restrict__ out,
         const float* __restrict__ W1, const float* __restrict__ b1,
         const float* __restrict__ W2, int step)
{
    extern __shared__ float smf[];
    float*    xs  = smf;                       // [20][6][34]
    uint32_t* Pu  = (uint32_t*)(smf + P_OFF);  // [128][68] tf32
    uint32_t* W1u = (uint32_t*)(smf + W1_OFF); // [128 hid][68] tf32 (k cols 0..63)
    uint32_t* W2u = (uint32_t*)(smf + W2_OFF); // [24 ch][132] tf32 (k cols 0..127)
    float*    b1s = smf + B1_OFF;              // [128]

    const int tid = threadIdx.x;
    const int w   = tid >> 5;                 // warp = tile row (ty)
    const int lane = tid & 31;
    const int g = lane >> 2;                  // group 0..7
    const int t = lane & 3;                   // thread-in-group 0..3
    const int bz  = blockIdx.z;
    const int by0 = blockIdx.y * TILE_H;
    const int bx0 = blockIdx.x * TILE_W;

    // ---- stage xs (reflect halo) + weights (tf32-rounded) ----
    const float* inb = in + bz * (CC * HH * WW);
    for (int i = tid; i < XS_ELEMS; i += NTHREADS) {
        int c   = i / (XS_ROWS * 34);
        int rem = i - c * (XS_ROWS * 34);
        int yy  = rem / 34;
        int xx  = rem - yy * 34;
        int gy  = refl(by0 + yy - 1, HH);
        int gx  = refl(bx0 + xx - 1, WW);
        xs[i] = inb[(c << 16) + (gy << 8) + gx];
    }
    for (int i = tid; i < KH * 60; i += NTHREADS) {
        int r = i / 60, c = i - r * 60;
        W1u[r * W1_STRIDE + c] = tf32r(W1[i]);
    }
    for (int i = tid; i < KH * 4; i += NTHREADS)
        W1u[(i >> 2) * W1_STRIDE + 60 + (i & 3)] = 0u;
    for (int i = tid; i < 24 * KH; i += NTHREADS) {
        int r = i >> 7, k = i & 127;
        W2u[r * W2_STRIDE + k] = (r < 20) ? tf32r(W2[r * KH + k]) : 0u;
    }
    if (tid < KH) b1s[tid] = b1[tid];
    __syncthreads();

    // ---- perceive own pixel -> P row (tf32) ----
    {
        uint32_t pt[64];
        const int tx = lane, ty = w;   // tile 32 wide x 4 high; tid -> (ty, tx)
        // NOTE: tx must be tid&31 which equals lane; ty = w. OK.
        #pragma unroll
        for (int c = 0; c < CC; c++) {
            const float* b = xs + (c * XS_ROWS + ty) * 34 + tx;
            float a00 = b[0],  a01 = b[1],  a02 = b[2];
            float a10 = b[34], a11 = b[35], a12 = b[36];
            float a20 = b[68], a21 = b[69], a22 = b[70];
            pt[c]          = tf32r(a11);
            pt[20 + 2 * c] = tf32r((a02 - a00 + 2.f * (a12 - a10) + a22 - a20) * 0.125f);
            pt[21 + 2 * c] = tf32r((a20 - a00 + 2.f * (a21 - a01) + a22 - a02) * 0.125f);
        }
        pt[60] = pt[61] = pt[62] = pt[63] = 0u;
        uint4* prow = (uint4*)(Pu + tid * P_STRIDE);
        #pragma unroll
        for (int j = 0; j < 16; j++)
            prow[j] = make_uint4(pt[4*j], pt[4*j+1], pt[4*j+2], pt[4*j+3]);
    }
    __syncwarp();

    // ---- cache A fragments (P rows of this warp) ----
    // m-tile m: rows R=w*32+m*16; a0=P[R+g][k0+t] a1=P[R+g+8][k0+t] a2=..t+4 a3=..
    uint32_t afr[2][8][4];
    #pragma unroll
    for (int m = 0; m < 2; m++) {
        int r0 = (w * 32 + m * 16 + g) * P_STRIDE;
        int r1 = r0 + 8 * P_STRIDE;
        #pragma unroll
        for (int ks = 0; ks < 8; ks++) {
            int c0 = ks * 8 + t;
            afr[m][ks][0] = Pu[r0 + c0];
            afr[m][ks][1] = Pu[r1 + c0];
            afr[m][ks][2] = Pu[r0 + c0 + 4];
            afr[m][ks][3] = Pu[r1 + c0 + 4];
        }
    }

    // ---- fused GEMM1 (P x W1^T) -> relu -> shuffle -> GEMM2 (H x W2^T) ----
    float acc2[2][3][4];
    #pragma unroll
    for (int m = 0; m < 2; m++)
        #pragma unroll
        for (int n = 0; n < 3; n++)
            #pragma unroll
            for (int j = 0; j < 4; j++) acc2[m][n][j] = 0.f;

    const int src  = (lane & ~3) | (t >> 1);
    const int src2 = src + 2;
    const int par  = t & 1;

    #pragma unroll 2
    for (int nt = 0; nt < 16; nt++) {
        // GEMM1 B frags: b0 = W1[nt*8+g][ks*8+t], b1 = ..[ks*8+t+4]
        uint32_t wb0[8], wb1[8];
        {
            int rw = (nt * 8 + g) * W1_STRIDE + t;
            #pragma unroll
            for (int ks = 0; ks < 8; ks++) {
                wb0[ks] = W1u[rw + ks * 8];
                wb1[ks] = W1u[rw + ks * 8 + 4];
            }
        }
        // GEMM2 B frags for k-step nt: b0 = W2[n2*8+g][nt*8+t], b1 = ..+4
        uint32_t vb0[3], vb1[3];
        {
            int cw = nt * 8 + t;
            #pragma unroll
            for (int n2 = 0; n2 < 3; n2++) {
                vb0[n2] = W2u[(n2 * 8 + g) * W2_STRIDE + cw];
                vb1[n2] = W2u[(n2 * 8 + g) * W2_STRIDE + cw + 4];
            }
        }
        float bc0 = b1s[nt * 8 + 2 * t];
        float bc1 = b1s[nt * 8 + 2 * t + 1];

        #pragma unroll
        for (int m = 0; m < 2; m++) {
            float c[4] = {0.f, 0.f, 0.f, 0.f};
            #pragma unroll
            for (int ks = 0; ks < 8; ks++)
                mma8(c, afr[m][ks], wb0[ks], wb1[ks]);

            uint32_t h0 = tf32r(fmaxf(c[0] + bc0, 0.f));
            uint32_t h1 = tf32r(fmaxf(c[1] + bc1, 0.f));
            uint32_t h2 = tf32r(fmaxf(c[2] + bc0, 0.f));
            uint32_t h3 = tf32r(fmaxf(c[3] + bc1, 0.f));

            // C-frag -> A-frag permutation (cols {2t,2t+1} -> {t,t+4})
            uint32_t a[4];
            uint32_t e, o;
            e = __shfl_sync(0xffffffffu, h0, src);
            o = __shfl_sync(0xffffffffu, h1, src);
            a[0] = par ? o : e;
            e = __shfl_sync(0xffffffffu, h2, src);
            o = __shfl_sync(0xffffffffu, h3, src);
            a[1] = par ? o : e;
            e = __shfl_sync(0xffffffffu, h0, src2);
            o = __shfl_sync(0xffffffffu, h1, src2);
            a[2] = par ? o : e;
            e = __shfl_sync(0xffffffffu, h2, src2);
            o = __shfl_sync(0xffffffffu, h3, src2);
            a[3] = par ? o : e;

            #pragma unroll
            for (int n2 = 0; n2 < 3; n2++)
                mma8(acc2[m][n2], a, vb0[n2], vb1[n2]);
        }
    }

    // ---- fire mask (4 pixels this thread holds in C-frags) + writeout ----
    uint32_t s0 = 0u, s1 = (uint32_t)step;
    tf2x32(0u, 42u, s0, s1);                   // fold_in(key(42), step)
    const int gy = by0 + w;
    float* outb = out + bz * (CC * HH * WW);

    #pragma unroll
    for (int m = 0; m < 2; m++) {
        #pragma unroll
        for (int half = 0; half < 2; half++) {
            int ptx = m * 16 + half * 8 + g;       // tile x of this held pixel
            int gx  = bx0 + ptx;
            int pidx = (bz << 16) + (gy << 8) + gx;
            uint32_t r0 = 0u, r1 = (uint32_t)pidx;
            tf2x32(s0, s1, r0, r1);
            bool fire = ((r0 ^ r1) & 0x80000000u) == 0u;

            #pragma unroll
            for (int n2 = 0; n2 < 3; n2++) {
                #pragma unroll
                for (int p = 0; p < 2; p++) {
                    int ch = n2 * 8 + 2 * t + p;
                    if (ch < 20) {
                        float v = xs[(ch * XS_ROWS + w + 1) * 34 + ptx + 1];
                        if (fire && ch >= 3) v += acc2[m][n2][half * 2 + p];
                        outb[(ch << 16) + (gy << 8) + gx] = v;
                    }
                }
            }
        }
    }
}

extern "C" void kernel_launch(void* const* d_in, const int* in_sizes, int n_in,
                              void* d_out, int out_size) {
    // Identify inputs by unique element counts:
    // x=10485760, W1=7680, b1=128, W2=2560, steps=1
    const float* x = nullptr; const float* W1 = nullptr;
    const float* b1 = nullptr; const float* W2 = nullptr;
    for (int i = 0; i < n_in; i++) {
        switch (in_sizes[i]) {
            case BB*CC*HH*WW: x  = (const float*)d_in[i]; break;
            case KH*60:       W1 = (const float*)d_in[i]; break;
            case KH:          b1 = (const float*)d_in[i]; break;
            case 20*KH:       W2 = (const float*)d_in[i]; break;
            default: break; // steps scalar; fixed at 64
        }
    }
    float* out = (float*)d_out;

    float *bufA = nullptr, *bufB = nullptr;
    cudaGetSymbolAddress((void**)&bufA, g_bufA);
    cudaGetSymbolAddress((void**)&bufB, g_bufB);

    cudaFuncSetAttribute(nca_step, cudaFuncAttributeMaxDynamicSharedMemorySize,
                         SMEM_BYTES);

    dim3 grid(WW / TILE_W, HH / TILE_H, BB);   // (8, 64, 8) = 4096 blocks
    const int STEPS = 64;
    for (int s = 0; s < STEPS; s++) {
        const float* src = (s == 0) ? x : ((s & 1) ? bufA : bufB);
        float* dst = (s == STEPS - 1) ? out : ((s & 1) ? bufB : bufA);
        nca_step<<<grid, NTHREADS, SMEM_BYTES>>>(src, dst, W1, b1, W2, s);
    }
}

// round 10
// speedup vs baseline: 1.8880x; 1.5574x over previous
#include <cuda_runtime.h>
#include <cstdint>

// NCA: x[8,20,256,256], W1[128,60], b1[128], W2[20,128], steps=64
// tf32 mma.sync path; persistent-ish blocks amortize weight staging.

#define BB 8
#define CC 20
#define HH 256
#define WW 256
#define KH 128

#define TILE_W 32
#define TILE_H 4
#define NTHREADS 128
#define NPIX 128
#define NTILES 4096          // (256/32) x (256/4) x 8
#define GRID_BLOCKS 296      // 2 per SM

#define XS_ROWS 6
#define XS_ELEMS (CC*XS_ROWS*34)   // 4080
#define P_STRIDE 68
#define W1_STRIDE 68
#define W2_STRIDE 132

#define P_OFF  4080
#define W1_OFF (P_OFF + NPIX*P_STRIDE)      // 12784
#define W2_OFF (W1_OFF + KH*W1_STRIDE)      // 21488
#define B1_OFF (W2_OFF + 24*W2_STRIDE)      // 24656
#define SMEM_FLOATS (B1_OFF + KH)           // 24784
#define SMEM_BYTES (SMEM_FLOATS*4)          // ~96.8 KB -> 2 blocks/SM

__device__ float g_bufA[BB*CC*HH*WW];
__device__ float g_bufB[BB*CC*HH*WW];

__device__ __forceinline__ uint32_t tf32r(float f) {
    uint32_t r;
    asm("cvt.rna.tf32.f32 %0, %1;" : "=r"(r) : "f"(f));
    return r;
}

__device__ __forceinline__ void mma8(float* c, const uint32_t* a,
                                     uint32_t b0, uint32_t b1) {
    asm volatile(
        "mma.sync.aligned.m16n8k8.row.col.f32.tf32.tf32.f32 "
        "{%0,%1,%2,%3}, {%4,%5,%6,%7}, {%8,%9}, {%0,%1,%2,%3};"
        : "+f"(c[0]), "+f"(c[1]), "+f"(c[2]), "+f"(c[3])
        : "r"(a[0]), "r"(a[1]), "r"(a[2]), "r"(a[3]), "r"(b0), "r"(b1));
}

__device__ __forceinline__ uint32_t rotl32(uint32_t v, int r) {
    return (v << r) | (v >> (32 - r));
}
// JAX threefry2x32 (20 rounds), bit-exact.
__device__ __forceinline__ void tf2x32(uint32_t k0, uint32_t k1,
                                       uint32_t& x0, uint32_t& x1) {
    uint32_t ks2 = k0 ^ k1 ^ 0x1BD11BDAu;
    x0 += k0; x1 += k1;
#define TFR(r) { x0 += x1; x1 = rotl32(x1, r); x1 ^= x0; }
    TFR(13) TFR(15) TFR(26) TFR(6)
    x0 += k1; x1 += ks2 + 1u;
    TFR(17) TFR(29) TFR(16) TFR(24)
    x0 += ks2; x1 += k0 + 2u;
    TFR(13) TFR(15) TFR(26) TFR(6)
    x0 += k0; x1 += k1 + 3u;
    TFR(17) TFR(29) TFR(16) TFR(24)
    x0 += k1; x1 += ks2 + 4u;
    TFR(13) TFR(15) TFR(26) TFR(6)
    x0 += ks2; x1 += k0 + 5u;
#undef TFR
}
__device__ __forceinline__ int refl(int v, int n) {
    v = (v < 0) ? -v : v;
    return (v >= n) ? (2 * n - 2 - v) : v;
}

__global__ void __launch_bounds__(NTHREADS, 2)
nca_step(const float* __restrict__ in, float* __restrict__ out,
         const float* __restrict__ W1, const float* __restrict__ b1,
         const float* __restrict__ W2, int step)
{
    extern __shared__ float smf[];
    float*    xs  = smf;                       // [20][6][34]
    uint32_t* Pu  = (uint32_t*)(smf + P_OFF);  // [128][68] tf32
    uint32_t* W1u = (uint32_t*)(smf + W1_OFF); // [128 hid][68] tf32
    uint32_t* W2u = (uint32_t*)(smf + W2_OFF); // [24 ch][132] tf32
    float*    b1s = smf + B1_OFF;              // [128]

    const int tid  = threadIdx.x;
    const int w    = tid >> 5;
    const int lane = tid & 31;
    const int g = lane >> 2;
    const int t = lane & 3;

    // ---- stage weights ONCE per block (tf32-rounded) ----
    for (int i = tid; i < KH * 60; i += NTHREADS) {
        int r = i / 60, c = i - r * 60;
        W1u[r * W1_STRIDE + c] = tf32r(W1[i]);
    }
    for (int i = tid; i < KH * 4; i += NTHREADS)
        W1u[(i >> 2) * W1_STRIDE + 60 + (i & 3)] = 0u;
    for (int i = tid; i < 24 * KH; i += NTHREADS) {
        int r = i >> 7, k = i & 127;
        W2u[r * W2_STRIDE + k] = (r < 20) ? tf32r(W2[r * KH + k]) : 0u;
    }
    if (tid < KH) b1s[tid] = b1[tid];

    // per-step key (once)
    uint32_t s0 = 0u, s1 = (uint32_t)step;
    tf2x32(0u, 42u, s0, s1);                   // fold_in(key(42), step)

    const int src  = (lane & ~3) | (t >> 1);
    const int src2 = src + 2;
    const int par  = t & 1;

    // ---- tile loop ----
    for (int tile = blockIdx.x; tile < NTILES; tile += GRID_BLOCKS) {
        const int ix = tile & 7;
        const int iy = (tile >> 3) & 63;
        const int bz = tile >> 9;
        const int bx0 = ix * TILE_W;
        const int by0 = iy * TILE_H;

        __syncthreads();   // protect xs/P reuse vs previous tile's readers

        // ---- stage xs (reflect halo) ----
        const float* inb = in + bz * (CC * HH * WW);
        for (int i = tid; i < XS_ELEMS; i += NTHREADS) {
            int c   = i / (XS_ROWS * 34);
            int rem = i - c * (XS_ROWS * 34);
            int yy  = rem / 34;
            int xx  = rem - yy * 34;
            int gy  = refl(by0 + yy - 1, HH);
            int gx  = refl(bx0 + xx - 1, WW);
            xs[i] = inb[(c << 16) + (gy << 8) + gx];
        }
        __syncthreads();

        // ---- perceive own pixel -> P row (tf32) ----
        {
            uint32_t pt[64];
            const int tx = lane, ty = w;
            #pragma unroll
            for (int c = 0; c < CC; c++) {
                const float* b = xs + (c * XS_ROWS + ty) * 34 + tx;
                float a00 = b[0],  a01 = b[1],  a02 = b[2];
                float a10 = b[34], a11 = b[35], a12 = b[36];
                float a20 = b[68], a21 = b[69], a22 = b[70];
                pt[c]          = tf32r(a11);
                pt[20 + 2 * c] = tf32r((a02 - a00 + 2.f * (a12 - a10) + a22 - a20) * 0.125f);
                pt[21 + 2 * c] = tf32r((a20 - a00 + 2.f * (a21 - a01) + a22 - a02) * 0.125f);
            }
            pt[60] = pt[61] = pt[62] = pt[63] = 0u;
            uint4* prow = (uint4*)(Pu + tid * P_STRIDE);
            #pragma unroll
            for (int j = 0; j < 16; j++)
                prow[j] = make_uint4(pt[4*j], pt[4*j+1], pt[4*j+2], pt[4*j+3]);
        }

        // ---- fire mask: one threefry per own pixel, warp ballot ----
        uint32_t fire_word;
        {
            int pidx = (bz << 16) + ((by0 + w) << 8) + (bx0 + lane);
            uint32_t r0 = 0u, r1 = (uint32_t)pidx;
            tf2x32(s0, s1, r0, r1);
            bool fire_own = ((r0 ^ r1) & 0x80000000u) == 0u;
            fire_word = __ballot_sync(0xffffffffu, fire_own);
        }
        __syncwarp();

        // ---- cache A fragments (P rows of this warp) ----
        uint32_t afr[2][8][4];
        #pragma unroll
        for (int m = 0; m < 2; m++) {
            int r0 = (w * 32 + m * 16 + g) * P_STRIDE;
            int r1 = r0 + 8 * P_STRIDE;
            #pragma unroll
            for (int ks = 0; ks < 8; ks++) {
                int c0 = ks * 8 + t;
                afr[m][ks][0] = Pu[r0 + c0];
                afr[m][ks][1] = Pu[r1 + c0];
                afr[m][ks][2] = Pu[r0 + c0 + 4];
                afr[m][ks][3] = Pu[r1 + c0 + 4];
            }
        }

        // ---- fused GEMM1 -> relu -> shuffle -> GEMM2 ----
        float acc2[2][3][4];
        #pragma unroll
        for (int m = 0; m < 2; m++)
            #pragma unroll
            for (int n = 0; n < 3; n++)
                #pragma unroll
                for (int j = 0; j < 4; j++) acc2[m][n][j] = 0.f;

        #pragma unroll 2
        for (int nt = 0; nt < 16; nt++) {
            uint32_t wb0[8], wb1[8];
            {
                int rw = (nt * 8 + g) * W1_STRIDE + t;
                #pragma unroll
                for (int ks = 0; ks < 8; ks++) {
                    wb0[ks] = W1u[rw + ks * 8];
                    wb1[ks] = W1u[rw + ks * 8 + 4];
                }
            }
            uint32_t vb0[3], vb1[3];
            {
                int cw = nt * 8 + t;
                #pragma unroll
                for (int n2 = 0; n2 < 3; n2++) {
                    vb0[n2] = W2u[(n2 * 8 + g) * W2_STRIDE + cw];
                    vb1[n2] = W2u[(n2 * 8 + g) * W2_STRIDE + cw + 4];
                }
            }
            float bc0 = b1s[nt * 8 + 2 * t];
            float bc1 = b1s[nt * 8 + 2 * t + 1];

            #pragma unroll
            for (int m = 0; m < 2; m++) {
                float c[4] = {0.f, 0.f, 0.f, 0.f};
                #pragma unroll
                for (int ks = 0; ks < 8; ks++)
                    mma8(c, afr[m][ks], wb0[ks], wb1[ks]);

                uint32_t h0 = tf32r(fmaxf(c[0] + bc0, 0.f));
                uint32_t h1 = tf32r(fmaxf(c[1] + bc1, 0.f));
                uint32_t h2 = tf32r(fmaxf(c[2] + bc0, 0.f));
                uint32_t h3 = tf32r(fmaxf(c[3] + bc1, 0.f));

                uint32_t a[4];
                uint32_t e, o;
                e = __shfl_sync(0xffffffffu, h0, src);
                o = __shfl_sync(0xffffffffu, h1, src);
                a[0] = par ? o : e;
                e = __shfl_sync(0xffffffffu, h2, src);
                o = __shfl_sync(0xffffffffu, h3, src);
                a[1] = par ? o : e;
                e = __shfl_sync(0xffffffffu, h0, src2);
                o = __shfl_sync(0xffffffffu, h1, src2);
                a[2] = par ? o : e;
                e = __shfl_sync(0xffffffffu, h2, src2);
                o = __shfl_sync(0xffffffffu, h3, src2);
                a[3] = par ? o : e;

                #pragma unroll
                for (int n2 = 0; n2 < 3; n2++)
                    mma8(acc2[m][n2], a, vb0[n2], vb1[n2]);
            }
        }

        // ---- writeout (mask bit from warp ballot) ----
        const int gy = by0 + w;
        float* outb = out + bz * (CC * HH * WW);

        #pragma unroll
        for (int m = 0; m < 2; m++) {
            #pragma unroll
            for (int half = 0; half < 2; half++) {
                int ptx = m * 16 + half * 8 + g;
                int gx  = bx0 + ptx;
                bool fire = (fire_word >> ptx) & 1u;

                #pragma unroll
                for (int n2 = 0; n2 < 3; n2++) {
                    #pragma unroll
                    for (int p = 0; p < 2; p++) {
                        int ch = n2 * 8 + 2 * t + p;
                        if (ch < 20) {
                            float v = xs[(ch * XS_ROWS + w + 1) * 34 + ptx + 1];
                            if (fire && ch >= 3) v += acc2[m][n2][half * 2 + p];
                            outb[(ch << 16) + (gy << 8) + gx] = v;
                        }
                    }
                }
            }
        }
    }
}

extern "C" void kernel_launch(void* const* d_in, const int* in_sizes, int n_in,
                              void* d_out, int out_size) {
    // Identify inputs by unique element counts:
    // x=10485760, W1=7680, b1=128, W2=2560, steps=1
    const float* x = nullptr; const float* W1 = nullptr;
    const float* b1 = nullptr; const float* W2 = nullptr;
    for (int i = 0; i < n_in; i++) {
        switch (in_sizes[i]) {
            case BB*CC*HH*WW: x  = (const float*)d_in[i]; break;
            case KH*60:       W1 = (const float*)d_in[i]; break;
            case KH:          b1 = (const float*)d_in[i]; break;
            case 20*KH:       W2 = (const float*)d_in[i]; break;
            default: break; // steps scalar; fixed at 64
        }
    }
    float* out = (float*)d_out;

    float *bufA = nullptr, *bufB = nullptr;
    cudaGetSymbolAddress((void**)&bufA, g_bufA);
    cudaGetSymbolAddress((void**)&bufB, g_bufB);

    cudaFuncSetAttribute(nca_step, cudaFuncAttributeMaxDynamicSharedMemorySize,
                         SMEM_BYTES);

    const int STEPS = 64;
    for (int s = 0; s < STEPS; s++) {
        const float* src = (s == 0) ? x : ((s & 1) ? bufA : bufB);
        float* dst = (s == STEPS - 1) ? out : ((s & 1) ? bufB : bufA);
        nca_step<<<GRID_BLOCKS, NTHREADS, SMEM_BYTES>>>(src, dst, W1, b1, W2, s);
    }
}

// round 11
// speedup vs baseline: 1.9729x; 1.0450x over previous
#include <cuda_runtime.h>
#include <cstdint>

// NCA: x[8,20,256,256], W1[128,60], b1[128], W2[20,128], steps=64
// tf32 mma.sync; weights pre-fragmented to global (L1-resident), 3 blocks/SM.

#define BB 8
#define CC 20
#define HH 256
#define WW 256
#define KH 128

#define TILE_W 32
#define TILE_H 4
#define NTHREADS 128
#define NPIX 128
#define NTILES 4096
#define GRID_BLOCKS 444      // 3 per SM

#define XS_ROWS 6
#define XS_ELEMS (CC*XS_ROWS*34)   // 4080 floats
#define P_STRIDE 72                // u32; pair layout, conflict-free LDS.64

#define P_OFF  4080                         // u32 offset; 16320B (16B aligned)
#define SMEM_FLOATS (P_OFF + NPIX*P_STRIDE) // 13296
#define SMEM_BYTES (SMEM_FLOATS*4)          // 53184 B -> 3 blocks/SM

__device__ float g_bufA[BB*CC*HH*WW];
__device__ float g_bufB[BB*CC*HH*WW];
// fragment-ordered weights (tf32 bits; biases as f32 bits)
__device__ uint4 g_w1frag[16][4][32];   // [nt][kpair][lane]
__device__ uint4 g_w2frag[16][2][32];   // [nt][half][lane]

__device__ __forceinline__ uint32_t tf32r(float f) {
    uint32_t r;
    asm("cvt.rna.tf32.f32 %0, %1;" : "=r"(r) : "f"(f));
    return r;
}

__device__ __forceinline__ void mma8(float* c, const uint32_t* a,
                                     uint32_t b0, uint32_t b1) {
    asm volatile(
        "mma.sync.aligned.m16n8k8.row.col.f32.tf32.tf32.f32 "
        "{%0,%1,%2,%3}, {%4,%5,%6,%7}, {%8,%9}, {%0,%1,%2,%3};"
        : "+f"(c[0]), "+f"(c[1]), "+f"(c[2]), "+f"(c[3])
        : "r"(a[0]), "r"(a[1]), "r"(a[2]), "r"(a[3]), "r"(b0), "r"(b1));
}

__device__ __forceinline__ uint32_t rotl32(uint32_t v, int r) {
    return (v << r) | (v >> (32 - r));
}
// JAX threefry2x32 (20 rounds), bit-exact.
__device__ __forceinline__ void tf2x32(uint32_t k0, uint32_t k1,
                                       uint32_t& x0, uint32_t& x1) {
    uint32_t ks2 = k0 ^ k1 ^ 0x1BD11BDAu;
    x0 += k0; x1 += k1;
#define TFR(r) { x0 += x1; x1 = rotl32(x1, r); x1 ^= x0; }
    TFR(13) TFR(15) TFR(26) TFR(6)
    x0 += k1; x1 += ks2 + 1u;
    TFR(17) TFR(29) TFR(16) TFR(24)
    x0 += ks2; x1 += k0 + 2u;
    TFR(13) TFR(15) TFR(26) TFR(6)
    x0 += k0; x1 += k1 + 3u;
    TFR(17) TFR(29) TFR(16) TFR(24)
    x0 += k1; x1 += ks2 + 4u;
    TFR(13) TFR(15) TFR(26) TFR(6)
    x0 += ks2; x1 += k0 + 5u;
#undef TFR
}
__device__ __forceinline__ int refl(int v, int n) {
    v = (v < 0) ? -v : v;
    return (v >= n) ? (2 * n - 2 - v) : v;
}

// ---- prep: build fragment-ordered weight arrays (once per launch) ----
__global__ void prep_frags(const float* __restrict__ W1,
                           const float* __restrict__ b1,
                           const float* __restrict__ W2) {
    int i = blockIdx.x * blockDim.x + threadIdx.x;
    if (i < 16 * 4 * 32) {
        int nt = i >> 7, kp = (i >> 5) & 3, lane = i & 31;
        int g = lane >> 2, t = lane & 3;
        int row = nt * 8 + g;
        int c0 = (2 * kp) * 8 + t;
        uint4 q;
        q.x = (c0      < 60) ? tf32r(W1[row * 60 + c0])      : 0u;
        q.y = (c0 + 4  < 60) ? tf32r(W1[row * 60 + c0 + 4])  : 0u;
        q.z = (c0 + 8  < 60) ? tf32r(W1[row * 60 + c0 + 8])  : 0u;
        q.w = (c0 + 12 < 60) ? tf32r(W1[row * 60 + c0 + 12]) : 0u;
        g_w1frag[nt][kp][lane] = q;
    } else if (i < 16 * 4 * 32 + 16 * 2 * 32) {
        int j = i - 16 * 4 * 32;
        int nt = j >> 6, half = (j >> 5) & 1, lane = j & 31;
        int g = lane >> 2, t = lane & 3;
        int k = nt * 8 + t;
        uint4 q;
        if (half == 0) {
            int r0 = g, r1 = 8 + g;
            q.x = (r0 < 20) ? tf32r(W2[r0 * KH + k])     : 0u;
            q.y = (r0 < 20) ? tf32r(W2[r0 * KH + k + 4]) : 0u;
            q.z = (r1 < 20) ? tf32r(W2[r1 * KH + k])     : 0u;
            q.w = (r1 < 20) ? tf32r(W2[r1 * KH + k + 4]) : 0u;
        } else {
            int r2 = 16 + g;
            q.x = (r2 < 20) ? tf32r(W2[r2 * KH + k])     : 0u;
            q.y = (r2 < 20) ? tf32r(W2[r2 * KH + k + 4]) : 0u;
            q.z = __float_as_uint(b1[nt * 8 + 2 * t]);
            q.w = __float_as_uint(b1[nt * 8 + 2 * t + 1]);
        }
        g_w2frag[nt][half][lane] = q;
    }
}

__global__ void __launch_bounds__(NTHREADS, 3)
nca_step(const float* __restrict__ in, float* __restrict__ out, int step)
{
    extern __shared__ float smf[];
    float*    xs = smf;                       // [20][6][34]
    uint32_t* Pu = (uint32_t*)(smf + P_OFF);  // [128][72] tf32 pair layout

    const int tid  = threadIdx.x;
    const int w    = tid >> 5;
    const int lane = tid & 31;
    const int g = lane >> 2;
    const int t = lane & 3;

    uint32_t s0 = 0u, s1 = (uint32_t)step;
    tf2x32(0u, 42u, s0, s1);                  // fold_in(key(42), step)

    const int src  = (lane & ~3) | (t >> 1);
    const int src2 = src + 2;
    const int par  = t & 1;

    for (int tile = blockIdx.x; tile < NTILES; tile += GRID_BLOCKS) {
        const int ix = tile & 7;
        const int iy = (tile >> 3) & 63;
        const int bz = tile >> 9;
        const int bx0 = ix * TILE_W;
        const int by0 = iy * TILE_H;

        __syncthreads();   // xs reuse vs previous tile's readers

        // ---- stage xs (reflect halo) ----
        const float* inb = in + bz * (CC * HH * WW);
        for (int i = tid; i < XS_ELEMS; i += NTHREADS) {
            int c   = i / (XS_ROWS * 34);
            int rem = i - c * (XS_ROWS * 34);
            int yy  = rem / 34;
            int xx  = rem - yy * 34;
            int gy  = refl(by0 + yy - 1, HH);
            int gx  = refl(bx0 + xx - 1, WW);
            xs[i] = inb[(c << 16) + (gy << 8) + gx];
        }
        __syncthreads();

        // ---- perceive own pixel -> P row (pair layout: u64 j = (col j>>2*8+j&3, +4)) ----
        {
            uint32_t pt[64];
            const int tx = lane, ty = w;
            #pragma unroll
            for (int c = 0; c < CC; c++) {
                const float* b = xs + (c * XS_ROWS + ty) * 34 + tx;
                float a00 = b[0],  a01 = b[1],  a02 = b[2];
                float a10 = b[34], a11 = b[35], a12 = b[36];
                float a20 = b[68], a21 = b[69], a22 = b[70];
                pt[c]          = tf32r(a11);
                pt[20 + 2 * c] = tf32r((a02 - a00 + 2.f * (a12 - a10) + a22 - a20) * 0.125f);
                pt[21 + 2 * c] = tf32r((a20 - a00 + 2.f * (a21 - a01) + a22 - a02) * 0.125f);
            }
            pt[60] = pt[61] = pt[62] = pt[63] = 0u;
            uint4* prow = (uint4*)(Pu + tid * P_STRIDE);
            #pragma unroll
            for (int v = 0; v < 16; v++) {
                int ks = v >> 1;
                int tA = 2 * (v & 1);
                prow[v] = make_uint4(pt[ks * 8 + tA],     pt[ks * 8 + tA + 4],
                                     pt[ks * 8 + tA + 1], pt[ks * 8 + tA + 5]);
            }
        }

        // ---- fire mask: one threefry per own pixel, warp ballot ----
        uint32_t fire_word;
        {
            int pidx = (bz << 16) + ((by0 + w) << 8) + (bx0 + lane);
            uint32_t r0 = 0u, r1 = (uint32_t)pidx;
            tf2x32(s0, s1, r0, r1);
            fire_word = __ballot_sync(0xffffffffu,
                                      ((r0 ^ r1) & 0x80000000u) == 0u);
        }
        __syncwarp();

        // ---- cache A fragments: (a0,a2),(a1,a3) via LDS.64 ----
        uint32_t afr[2][8][4];
        #pragma unroll
        for (int m = 0; m < 2; m++) {
            int r0 = (w * 32 + m * 16 + g) * P_STRIDE;
            int r1 = r0 + 8 * P_STRIDE;
            #pragma unroll
            for (int ks = 0; ks < 8; ks++) {
                int o = 8 * ks + 2 * t;
                uint2 lo = *(const uint2*)(Pu + r0 + o);
                uint2 hi = *(const uint2*)(Pu + r1 + o);
                afr[m][ks][0] = lo.x;   // P[r0][ks*8+t]
                afr[m][ks][2] = lo.y;   // P[r0][ks*8+t+4]
                afr[m][ks][1] = hi.x;
                afr[m][ks][3] = hi.y;
            }
        }

        // ---- fused GEMM1 -> relu -> shuffle -> GEMM2 ----
        float acc2[2][3][4];
        #pragma unroll
        for (int m = 0; m < 2; m++)
            #pragma unroll
            for (int n = 0; n < 3; n++)
                #pragma unroll
                for (int j = 0; j < 4; j++) acc2[m][n][j] = 0.f;

        #pragma unroll 2
        for (int nt = 0; nt < 16; nt++) {
            uint32_t wb0[8], wb1[8];
            #pragma unroll
            for (int kp = 0; kp < 4; kp++) {
                uint4 q = g_w1frag[nt][kp][lane];
                wb0[2*kp]   = q.x;  wb1[2*kp]   = q.y;
                wb0[2*kp+1] = q.z;  wb1[2*kp+1] = q.w;
            }
            uint4 v0 = g_w2frag[nt][0][lane];
            uint4 v1 = g_w2frag[nt][1][lane];
            float bc0 = __uint_as_float(v1.z);
            float bc1 = __uint_as_float(v1.w);

            #pragma unroll
            for (int m = 0; m < 2; m++) {
                float ca[4] = {0.f, 0.f, 0.f, 0.f};
                float cb[4] = {0.f, 0.f, 0.f, 0.f};
                #pragma unroll
                for (int ks = 0; ks < 4; ks++) {
                    mma8(ca, afr[m][ks],     wb0[ks],     wb1[ks]);
                    mma8(cb, afr[m][ks + 4], wb0[ks + 4], wb1[ks + 4]);
                }
                uint32_t h0 = tf32r(fmaxf(ca[0] + cb[0] + bc0, 0.f));
                uint32_t h1 = tf32r(fmaxf(ca[1] + cb[1] + bc1, 0.f));
                uint32_t h2 = tf32r(fmaxf(ca[2] + cb[2] + bc0, 0.f));
                uint32_t h3 = tf32r(fmaxf(ca[3] + cb[3] + bc1, 0.f));

                uint32_t a[4];
                uint32_t e, o;
                e = __shfl_sync(0xffffffffu, h0, src);
                o = __shfl_sync(0xffffffffu, h1, src);
                a[0] = par ? o : e;
                e = __shfl_sync(0xffffffffu, h2, src);
                o = __shfl_sync(0xffffffffu, h3, src);
                a[1] = par ? o : e;
                e = __shfl_sync(0xffffffffu, h0, src2);
                o = __shfl_sync(0xffffffffu, h1, src2);
                a[2] = par ? o : e;
                e = __shfl_sync(0xffffffffu, h2, src2);
                o = __shfl_sync(0xffffffffu, h3, src2);
                a[3] = par ? o : e;

                mma8(acc2[m][0], a, v0.x, v0.y);
                mma8(acc2[m][1], a, v0.z, v0.w);
                mma8(acc2[m][2], a, v1.x, v1.y);
            }
        }

        // ---- writeout ----
        const int gy = by0 + w;
        float* outb = out + bz * (CC * HH * WW);

        #pragma unroll
        for (int m = 0; m < 2; m++) {
            #pragma unroll
            for (int half = 0; half < 2; half++) {
                int ptx = m * 16 + half * 8 + g;
                int gx  = bx0 + ptx;
                bool fire = (fire_word >> ptx) & 1u;

                #pragma unroll
                for (int n2 = 0; n2 < 3; n2++) {
                    #pragma unroll
                    for (int p = 0; p < 2; p++) {
                        int ch = n2 * 8 + 2 * t + p;
                        if (ch < 20) {
                            float v = xs[(ch * XS_ROWS + w + 1) * 34 + ptx + 1];
                            if (fire && ch >= 3) v += acc2[m][n2][half * 2 + p];
                            outb[(ch << 16) + (gy << 8) + gx] = v;
                        }
                    }
                }
            }
        }
    }
}

extern "C" void kernel_launch(void* const* d_in, const int* in_sizes, int n_in,
                              void* d_out, int out_size) {
    // Identify inputs by unique element counts:
    // x=10485760, W1=7680, b1=128, W2=2560, steps=1
    const float* x = nullptr; const float* W1 = nullptr;
    const float* b1 = nullptr; const float* W2 = nullptr;
    for (int i = 0; i < n_in; i++) {
        switch (in_sizes[i]) {
            case BB*CC*HH*WW: x  = (const float*)d_in[i]; break;
            case KH*60:       W1 = (const float*)d_in[i]; break;
            case KH:          b1 = (const float*)d_in[i]; break;
            case 20*KH:       W2 = (const float*)d_in[i]; break;
            default: break; // steps scalar; fixed at 64
        }
    }
    float* out = (float*)d_out;

    float *bufA = nullptr, *bufB = nullptr;
    cudaGetSymbolAddress((void**)&bufA, g_bufA);
    cudaGetSymbolAddress((void**)&bufB, g_bufB);

    prep_frags<<<12, 256>>>(W1, b1, W2);   // 3072 threads >= 2048+1024

    cudaFuncSetAttribute(nca_step, cudaFuncAttributeMaxDynamicSharedMemorySize,
                         SMEM_BYTES);

    const int STEPS = 64;
    for (int s = 0; s < STEPS; s++) {
        const float* src = (s == 0) ? x : ((s & 1) ? bufA : bufB);
        float* dst = (s == STEPS - 1) ? out : ((s & 1) ? bufB : bufA);
        nca_step<<<GRID_BLOCKS, NTHREADS, SMEM_BYTES>>>(src, dst, s);
    }
}

// round 12
// speedup vs baseline: 2.5102x; 1.2723x over previous
#include <cuda_runtime.h>
#include <cstdint>

// NCA: x[8,20,256,256], W1[128,60], b1[128], W2[20,128], steps=64
// tf32 mma.sync; 32x8 tile, 2 GEMM passes; fragment weights in global (L1-hit).

#define BB 8
#define CC 20
#define HH 256
#define WW 256
#define KH 128

#define TILE_W 32
#define TILE_H 8
#define NTHREADS 128
#define NTILES 2048          // 8 x 32 x 8
#define GRID_BLOCKS 444      // 3 per SM

#define XS_ROWS 10
#define NPOS (XS_ROWS*34)          // 340 spatial positions
#define XS_ELEMS (CC*NPOS)         // 6800 floats
#define P_STRIDE 72                // u32; pair layout, conflict-free LDS.64

#define P_OFF  6800                          // float offset (27200B, 16B aligned)
#define SMEM_FLOATS (P_OFF + 128*P_STRIDE)   // 16016
#define SMEM_BYTES (SMEM_FLOATS*4)           // 64064 B -> 3 blocks/SM

__device__ float g_bufA[BB*CC*HH*WW];
__device__ float g_bufB[BB*CC*HH*WW];
__device__ uint4 g_w1frag[16][4][32];   // [nt][kpair][lane]
__device__ uint4 g_w2frag[16][2][32];   // [nt][half][lane]

__device__ __forceinline__ uint32_t tf32r(float f) {
    uint32_t r;
    asm("cvt.rna.tf32.f32 %0, %1;" : "=r"(r) : "f"(f));
    return r;
}

__device__ __forceinline__ void mma8(float* c, const uint32_t* a,
                                     uint32_t b0, uint32_t b1) {
    asm volatile(
        "mma.sync.aligned.m16n8k8.row.col.f32.tf32.tf32.f32 "
        "{%0,%1,%2,%3}, {%4,%5,%6,%7}, {%8,%9}, {%0,%1,%2,%3};"
        : "+f"(c[0]), "+f"(c[1]), "+f"(c[2]), "+f"(c[3])
        : "r"(a[0]), "r"(a[1]), "r"(a[2]), "r"(a[3]), "r"(b0), "r"(b1));
}

__device__ __forceinline__ uint32_t rotl32(uint32_t v, int r) {
    return (v << r) | (v >> (32 - r));
}
// JAX threefry2x32 (20 rounds), bit-exact.
__device__ __forceinline__ void tf2x32(uint32_t k0, uint32_t k1,
                                       uint32_t& x0, uint32_t& x1) {
    uint32_t ks2 = k0 ^ k1 ^ 0x1BD11BDAu;
    x0 += k0; x1 += k1;
#define TFR(r) { x0 += x1; x1 = rotl32(x1, r); x1 ^= x0; }
    TFR(13) TFR(15) TFR(26) TFR(6)
    x0 += k1; x1 += ks2 + 1u;
    TFR(17) TFR(29) TFR(16) TFR(24)
    x0 += ks2; x1 += k0 + 2u;
    TFR(13) TFR(15) TFR(26) TFR(6)
    x0 += k0; x1 += k1 + 3u;
    TFR(17) TFR(29) TFR(16) TFR(24)
    x0 += k1; x1 += ks2 + 4u;
    TFR(13) TFR(15) TFR(26) TFR(6)
    x0 += ks2; x1 += k0 + 5u;
#undef TFR
}
__device__ __forceinline__ int refl(int v, int n) {
    v = (v < 0) ? -v : v;
    return (v >= n) ? (2 * n - 2 - v) : v;
}

// ---- prep: fragment-ordered weights (once per launch) ----
__global__ void prep_frags(const float* __restrict__ W1,
                           const float* __restrict__ b1,
                           const float* __restrict__ W2) {
    int i = blockIdx.x * blockDim.x + threadIdx.x;
    if (i < 16 * 4 * 32) {
        int nt = i >> 7, kp = (i >> 5) & 3, lane = i & 31;
        int g = lane >> 2, t = lane & 3;
        int row = nt * 8 + g;
        int c0 = (2 * kp) * 8 + t;
        uint4 q;
        q.x = (c0      < 60) ? tf32r(W1[row * 60 + c0])      : 0u;
        q.y = (c0 + 4  < 60) ? tf32r(W1[row * 60 + c0 + 4])  : 0u;
        q.z = (c0 + 8  < 60) ? tf32r(W1[row * 60 + c0 + 8])  : 0u;
        q.w = (c0 + 12 < 60) ? tf32r(W1[row * 60 + c0 + 12]) : 0u;
        g_w1frag[nt][kp][lane] = q;
    } else if (i < 16 * 4 * 32 + 16 * 2 * 32) {
        int j = i - 16 * 4 * 32;
        int nt = j >> 6, half = (j >> 5) & 1, lane = j & 31;
        int g = lane >> 2, t = lane & 3;
        int k = nt * 8 + t;
        uint4 q;
        if (half == 0) {
            int r0 = g, r1 = 8 + g;
            q.x = (r0 < 20) ? tf32r(W2[r0 * KH + k])     : 0u;
            q.y = (r0 < 20) ? tf32r(W2[r0 * KH + k + 4]) : 0u;
            q.z = (r1 < 20) ? tf32r(W2[r1 * KH + k])     : 0u;
            q.w = (r1 < 20) ? tf32r(W2[r1 * KH + k + 4]) : 0u;
        } else {
            int r2 = 16 + g;
            q.x = (r2 < 20) ? tf32r(W2[r2 * KH + k])     : 0u;
            q.y = (r2 < 20) ? tf32r(W2[r2 * KH + k + 4]) : 0u;
            q.z = __float_as_uint(b1[nt * 8 + 2 * t]);
            q.w = __float_as_uint(b1[nt * 8 + 2 * t + 1]);
        }
        g_w2frag[nt][half][lane] = q;
    }
}

__global__ void __launch_bounds__(NTHREADS, 3)
nca_step(const float* __restrict__ in, float* __restrict__ out, int step)
{
    extern __shared__ float smf[];
    float*    xs = smf;                       // [20][10][34]
    uint32_t* Pu = (uint32_t*)(smf + P_OFF);  // [128][72] tf32 pair layout

    const int tid  = threadIdx.x;
    const int w    = tid >> 5;
    const int lane = tid & 31;
    const int g = lane >> 2;
    const int t = lane & 3;

    uint32_t s0 = 0u, s1 = (uint32_t)step;
    tf2x32(0u, 42u, s0, s1);                  // fold_in(key(42), step)

    const int src  = (lane & ~3) | (t >> 1);
    const int src2 = src + 2;
    const int par  = t & 1;

    for (int tile = blockIdx.x; tile < NTILES; tile += GRID_BLOCKS) {
        const int ix = tile & 7;
        const int iy = (tile >> 3) & 31;
        const int bz = tile >> 8;
        const int bx0 = ix * TILE_W;
        const int by0 = iy * TILE_H;

        __syncthreads();   // xs reuse vs previous tile's readers

        // ---- stage xs: 1 div per spatial position, 20-ch pointer loop ----
        const float* inb = in + bz * (CC * HH * WW);
        for (int pp = tid; pp < NPOS; pp += NTHREADS) {
            int yy = pp / 34;
            int xx = pp - yy * 34;
            int gy = refl(by0 + yy - 1, HH);
            int gx = refl(bx0 + xx - 1, WW);
            const float* src_p = inb + (gy << 8) + gx;
            float* dst_p = xs + pp;
            #pragma unroll
            for (int c = 0; c < CC; c++)
                dst_p[c * NPOS] = src_p[c << 16];
        }
        __syncthreads();

        // ---- two GEMM passes over the 32x8 tile ----
        #pragma unroll 1
        for (int mo = 0; mo < 2; mo++) {
            const int yrow = mo * 4 + w;          // pixel y within tile

            // perceive own pixel -> P row (pair layout)
            {
                uint32_t pt[64];
                #pragma unroll
                for (int c = 0; c < CC; c++) {
                    const float* b = xs + (c * XS_ROWS + yrow) * 34 + lane;
                    float a00 = b[0],  a01 = b[1],  a02 = b[2];
                    float a10 = b[34], a11 = b[35], a12 = b[36];
                    float a20 = b[68], a21 = b[69], a22 = b[70];
                    pt[c]          = tf32r(a11);
                    pt[20 + 2 * c] = tf32r((a02 - a00 + 2.f * (a12 - a10) + a22 - a20) * 0.125f);
                    pt[21 + 2 * c] = tf32r((a20 - a00 + 2.f * (a21 - a01) + a22 - a02) * 0.125f);
                }
                pt[60] = pt[61] = pt[62] = pt[63] = 0u;
                uint4* prow = (uint4*)(Pu + tid * P_STRIDE);
                #pragma unroll
                for (int v = 0; v < 16; v++) {
                    int ks = v >> 1;
                    int tA = 2 * (v & 1);
                    prow[v] = make_uint4(pt[ks * 8 + tA],     pt[ks * 8 + tA + 4],
                                         pt[ks * 8 + tA + 1], pt[ks * 8 + tA + 5]);
                }
            }

            // fire mask: one threefry for own pixel, warp ballot
            uint32_t fire_word;
            {
                int pidx = (bz << 16) + ((by0 + yrow) << 8) + (bx0 + lane);
                uint32_t r0 = 0u, r1 = (uint32_t)pidx;
                tf2x32(s0, s1, r0, r1);
                fire_word = __ballot_sync(0xffffffffu,
                                          ((r0 ^ r1) & 0x80000000u) == 0u);
            }
            __syncwarp();   // P rows (warp-local) visible

            // cache A fragments via LDS.64
            uint32_t afr[2][8][4];
            #pragma unroll
            for (int m = 0; m < 2; m++) {
                int r0 = (w * 32 + m * 16 + g) * P_STRIDE;
                int r1 = r0 + 8 * P_STRIDE;
                #pragma unroll
                for (int ks = 0; ks < 8; ks++) {
                    int o = 8 * ks + 2 * t;
                    uint2 lo = *(const uint2*)(Pu + r0 + o);
                    uint2 hi = *(const uint2*)(Pu + r1 + o);
                    afr[m][ks][0] = lo.x;
                    afr[m][ks][2] = lo.y;
                    afr[m][ks][1] = hi.x;
                    afr[m][ks][3] = hi.y;
                }
            }

            // fused GEMM1 -> relu -> shuffle -> GEMM2
            float acc2[2][3][4];
            #pragma unroll
            for (int m = 0; m < 2; m++)
                #pragma unroll
                for (int n = 0; n < 3; n++)
                    #pragma unroll
                    for (int j = 0; j < 4; j++) acc2[m][n][j] = 0.f;

            #pragma unroll 2
            for (int nt = 0; nt < 16; nt++) {
                uint32_t wb0[8], wb1[8];
                #pragma unroll
                for (int kp = 0; kp < 4; kp++) {
                    uint4 q = g_w1frag[nt][kp][lane];
                    wb0[2*kp]   = q.x;  wb1[2*kp]   = q.y;
                    wb0[2*kp+1] = q.z;  wb1[2*kp+1] = q.w;
                }
                uint4 v0 = g_w2frag[nt][0][lane];
                uint4 v1 = g_w2frag[nt][1][lane];
                float bc0 = __uint_as_float(v1.z);
                float bc1 = __uint_as_float(v1.w);

                #pragma unroll
                for (int m = 0; m < 2; m++) {
                    float ca[4] = {0.f, 0.f, 0.f, 0.f};
                    float cb[4] = {0.f, 0.f, 0.f, 0.f};
                    #pragma unroll
                    for (int ks = 0; ks < 4; ks++) {
                        mma8(ca, afr[m][ks],     wb0[ks],     wb1[ks]);
                        mma8(cb, afr[m][ks + 4], wb0[ks + 4], wb1[ks + 4]);
                    }
                    // raw f32 bits: tf32 MMA reads top 19 bits (RZ truncation)
                    uint32_t h0 = __float_as_uint(fmaxf(ca[0] + cb[0] + bc0, 0.f));
                    uint32_t h1 = __float_as_uint(fmaxf(ca[1] + cb[1] + bc1, 0.f));
                    uint32_t h2 = __float_as_uint(fmaxf(ca[2] + cb[2] + bc0, 0.f));
                    uint32_t h3 = __float_as_uint(fmaxf(ca[3] + cb[3] + bc1, 0.f));

                    uint32_t a[4];
                    uint32_t e, o;
                    e = __shfl_sync(0xffffffffu, h0, src);
                    o = __shfl_sync(0xffffffffu, h1, src);
                    a[0] = par ? o : e;
                    e = __shfl_sync(0xffffffffu, h2, src);
                    o = __shfl_sync(0xffffffffu, h3, src);
                    a[1] = par ? o : e;
                    e = __shfl_sync(0xffffffffu, h0, src2);
                    o = __shfl_sync(0xffffffffu, h1, src2);
                    a[2] = par ? o : e;
                    e = __shfl_sync(0xffffffffu, h2, src2);
                    o = __shfl_sync(0xffffffffu, h3, src2);
                    a[3] = par ? o : e;

                    mma8(acc2[m][0], a, v0.x, v0.y);
                    mma8(acc2[m][1], a, v0.z, v0.w);
                    mma8(acc2[m][2], a, v1.x, v1.y);
                }
            }

            // writeout
            const int gy = by0 + yrow;
            float* outb = out + bz * (CC * HH * WW);

            #pragma unroll
            for (int m = 0; m < 2; m++) {
                #pragma unroll
                for (int half = 0; half < 2; half++) {
                    int ptx = m * 16 + half * 8 + g;
                    int gx  = bx0 + ptx;
                    bool fire = (fire_word >> ptx) & 1u;

                    #pragma unroll
                    for (int n2 = 0; n2 < 3; n2++) {
                        #pragma unroll
                        for (int p = 0; p < 2; p++) {
                            int ch = n2 * 8 + 2 * t + p;
                            if (ch < 20) {
                                float v = xs[(ch * XS_ROWS + yrow + 1) * 34 + ptx + 1];
                                if (fire && ch >= 3) v += acc2[m][n2][half * 2 + p];
                                outb[(ch << 16) + (gy << 8) + gx] = v;
                            }
                        }
                    }
                }
            }
        }
    }
}

extern "C" void kernel_launch(void* const* d_in, const int* in_sizes, int n_in,
                              void* d_out, int out_size) {
    // Identify inputs by unique element counts:
    // x=10485760, W1=7680, b1=128, W2=2560, steps=1
    const float* x = nullptr; const float* W1 = nullptr;
    const float* b1 = nullptr; const float* W2 = nullptr;
    for (int i = 0; i < n_in; i++) {
        switch (in_sizes[i]) {
            case BB*CC*HH*WW: x  = (const float*)d_in[i]; break;
            case KH*60:       W1 = (const float*)d_in[i]; break;
            case KH:          b1 = (const float*)d_in[i]; break;
            case 20*KH:       W2 = (const float*)d_in[i]; break;
            default: break; // steps scalar; fixed at 64
        }
    }
    float* out = (float*)d_out;

    float *bufA = nullptr, *bufB = nullptr;
    cudaGetSymbolAddress((void**)&bufA, g_bufA);
    cudaGetSymbolAddress((void**)&bufB, g_bufB);

    prep_frags<<<12, 256>>>(W1, b1, W2);

    cudaFuncSetAttribute(nca_step, cudaFuncAttributeMaxDynamicSharedMemorySize,
                         SMEM_BYTES);

    const int STEPS = 64;
    for (int s = 0; s < STEPS; s++) {
        const float* src = (s == 0) ? x : ((s & 1) ? bufA : bufB);
        float* dst = (s == STEPS - 1) ? out : ((s & 1) ? bufB : bufA);
        nca_step<<<GRID_BLOCKS, NTHREADS, SMEM_BYTES>>>(src, dst, s);
    }
}